// round 14
// baseline (speedup 1.0000x reference)
#include <cuda_runtime.h>
#include <cuda_bf16.h>

// Fixed problem constants:
//   SIGMA=8 -> 1/(2*sigma^2)=1/128, C_SIZE=512, STRIDE=8 -> 64x64 grid,
//   cood[k]=8k+4, B=16, N=512, BG_RATIO=0.15, EPS=1e-5
//   out[b, p, i*64+j], p in [0,512], fp32, [16, 513, 4096]

#define CGRID   64
#define NPTS    512
#define PCHUNK  32
#define NCHUNK  (NPTS / PCHUNK)     // 16
#define BFIX    16
#define MPIX    (CGRID * CGRID)     // 4096
#define KINV    (1.0f / 128.0f)

// Static scratch (no runtime allocation allowed)
__device__ float g_psum[BFIX * NCHUNK * MPIX];   // 4 MB per-chunk partial sums
__device__ float g_pmax[BFIX * NCHUNK * MPIX];   // 4 MB per-chunk max products
__device__ float g_invt[BFIX * MPIX];            // 1/denominator per pixel
__device__ int   g_done[BFIX];                   // partial blocks retired per image

// ---------------------------------------------------------------------------
// K1 (fused): per (b, chunk, 16-row tile) partial exp-sum + max product.
//   The LAST-arriving block of each image also performs that image's combine
//   (chunk reduction -> invt + background plane) — threadFenceReduction
//   pattern, no spinning, counters self-reset for graph replay.
// ---------------------------------------------------------------------------
__global__ __launch_bounds__(256)
void k_partial(const float* __restrict__ points,
               const float* __restrict__ st_sizes,
               float* __restrict__ out)
{
    const int b   = blockIdx.z;
    const int c   = blockIdx.y;
    const int i0  = blockIdx.x * 16;
    const int tid = threadIdx.x;
    const int ti  = tid >> 4;      // 0..15 row in tile
    const int jg  = tid & 15;      // owns j = jg*4 + {0..3}

    __shared__ float Ex_s[PCHUNK * CGRID];     // 8 KB  [p][j]
    __shared__ float Ey_s[PCHUNK * 16];        // 2 KB  [p][ti]  (transposed)
    __shared__ bool  amLast;

    const float* ptb = points + (b * NPTS + c * PCHUNK) * 2;

    // Ex fill: p uniform per warp -> broadcast LDG (L1-hit).
    #pragma unroll
    for (int k = 0; k < (PCHUNK * CGRID) / 256; ++k) {   // 8 iters
        int idx = tid + k * 256;
        int p = idx >> 6, jj = idx & 63;
        float dx = ptb[p * 2] - (float)(jj * 8 + 4);
        Ex_s[idx] = __expf(-dx * dx * KINV);
    }
    // Ey fill (transposed layout [p][ti]).
    #pragma unroll
    for (int k = 0; k < (PCHUNK * 16) / 256; ++k) {      // 2 iters
        int idx = tid + k * 256;
        int p = idx >> 4, ii = idx & 15;
        float dy = ptb[p * 2 + 1] - (float)((i0 + ii) * 8 + 4);
        Ey_s[idx] = __expf(-dy * dy * KINV);
    }
    __syncthreads();

    float4 sum = make_float4(0.f, 0.f, 0.f, 0.f);
    float4 mx  = make_float4(0.f, 0.f, 0.f, 0.f);
    const float4* Ex4 = (const float4*)Ex_s;

    #pragma unroll 8
    for (int p = 0; p < PCHUNK; ++p) {
        float  ey = Ey_s[p * 16 + ti];          // adjacent words -> broadcast
        float4 ex = Ex4[p * 16 + jg];
        float p0 = ey * ex.x;
        float p1 = ey * ex.y;
        float p2 = ey * ex.z;
        float p3 = ey * ex.w;
        sum.x += p0; sum.y += p1; sum.z += p2; sum.w += p3;
        mx.x = fmaxf(mx.x, p0); mx.y = fmaxf(mx.y, p1);
        mx.z = fmaxf(mx.z, p2); mx.w = fmaxf(mx.w, p3);
    }

    int o = (b * NCHUNK + c) * MPIX + (i0 + ti) * CGRID + jg * 4;
    *(float4*)(g_psum + o) = sum;
    *(float4*)(g_pmax + o) = mx;

    // ---- last-block epilogue: combine image b --------------------------
    __threadfence();
    if (tid == 0) {
        int t = atomicAdd(&g_done[b], 1);
        amLast = (t == (CGRID / 16) * NCHUNK - 1);   // 64 blocks per image
        if (amLast) g_done[b] = 0;                   // reset for next replay
    }
    __syncthreads();
    if (!amLast) return;

    float sc = st_sizes[b] * 0.15f;
    float ss = sc * sc;
    const float4* ps = (const float4*)g_psum;
    const float4* pm = (const float4*)g_pmax;

    #pragma unroll
    for (int q = 0; q < 4; ++q) {
        int r = q * 256 + tid;                  // float4 index within image
        int base = b * NCHUNK * 1024 + r;

        float4 s4 = make_float4(0.f, 0.f, 0.f, 0.f);
        float4 m4 = make_float4(0.f, 0.f, 0.f, 0.f);
        #pragma unroll
        for (int cc = 0; cc < NCHUNK; ++cc) {
            float4 s = ps[base + cc * 1024];
            float4 m = pm[base + cc * 1024];
            s4.x += s.x; s4.y += s.y; s4.z += s.z; s4.w += s.w;
            m4.x = fmaxf(m4.x, m.x); m4.y = fmaxf(m4.y, m.y);
            m4.z = fmaxf(m4.z, m.z); m4.w = fmaxf(m4.w, m.w);
        }

        float4 invt, bgp;
        {
            float mind = -128.0f * __logf(fmaxf(m4.x, 1e-38f));
            float ebg = __expf(-(ss / (mind + 1e-5f)) * KINV);
            float iv = 1.0f / (s4.x + ebg); invt.x = iv; bgp.x = ebg * iv;
        }
        {
            float mind = -128.0f * __logf(fmaxf(m4.y, 1e-38f));
            float ebg = __expf(-(ss / (mind + 1e-5f)) * KINV);
            float iv = 1.0f / (s4.y + ebg); invt.y = iv; bgp.y = ebg * iv;
        }
        {
            float mind = -128.0f * __logf(fmaxf(m4.z, 1e-38f));
            float ebg = __expf(-(ss / (mind + 1e-5f)) * KINV);
            float iv = 1.0f / (s4.z + ebg); invt.z = iv; bgp.z = ebg * iv;
        }
        {
            float mind = -128.0f * __logf(fmaxf(m4.w, 1e-38f));
            float ebg = __expf(-(ss / (mind + 1e-5f)) * KINV);
            float iv = 1.0f / (s4.w + ebg); invt.w = iv; bgp.w = ebg * iv;
        }

        ((float4*)g_invt)[b * 1024 + r] = invt;
        __stcs(((float4*)out) + (b * 513 + 512) * 1024 + r, bgp);
    }
}

// ---------------------------------------------------------------------------
// K2: normalized writes. Block = (b, group of 8 planes) -> fully contiguous
//     128 KB output span per block, streaming stores. (At the effective HBM
//     write ceiling ~6.1 TB/s; proven best of 6 variants.)
// ---------------------------------------------------------------------------
#define PGRP 8

__global__ __launch_bounds__(256)
void k_write(const float* __restrict__ points, float* __restrict__ out)
{
    const int b   = blockIdx.x >> 6;            // 0..15
    const int pg  = blockIdx.x & 63;            // plane group: p = pg*8 + pl
    const int tid = threadIdx.x;

    __shared__ float Ex_s[PGRP][CGRID];         // 2 KB
    __shared__ float Ey_s[PGRP][CGRID];         // 2 KB

    // Fill per-plane Ex/Ey rows: 8 planes * 64 cells * 2 tables = 1024 exps.
    #pragma unroll
    for (int k = 0; k < 4; ++k) {
        int idx  = tid + k * 256;               // 0..1023
        int pl   = idx >> 7;
        int rest = idx & 127;
        int t    = rest >> 6;                   // 0: Ex (x), 1: Ey (y)
        int cell = rest & 63;
        int p    = pg * PGRP + pl;
        float coord = points[(b * NPTS + p) * 2 + t];
        float d = coord - (float)(cell * 8 + 4);
        float e = __expf(-d * d * KINV);
        if (t) Ey_s[pl][cell] = e; else Ex_s[pl][cell] = e;
    }

    // invt for this image: each thread holds 4 float4 (covers its 4 f-slots).
    const float4* iv4 = (const float4*)g_invt + b * 1024;
    float4 invt[4];
    #pragma unroll
    for (int k = 0; k < 4; ++k)
        invt[k] = __ldg(iv4 + tid + k * 256);

    __syncthreads();

    float4* op = (float4*)out + ((size_t)b * 513 + pg * PGRP) * 1024;

    #pragma unroll
    for (int pl = 0; pl < PGRP; ++pl) {
        const float4* Ex4 = (const float4*)Ex_s[pl];
        #pragma unroll
        for (int k = 0; k < 4; ++k) {
            int f  = tid + k * 256;             // float4 index within plane
            int i  = f >> 4;
            int jg = f & 15;
            float  ey = Ey_s[pl][i];
            float4 ex = Ex4[jg];
            float4 v;
            v.x = (ey * ex.x) * invt[k].x;
            v.y = (ey * ex.y) * invt[k].y;
            v.z = (ey * ex.z) * invt[k].z;
            v.w = (ey * ex.w) * invt[k].w;
            __stcs(op + (size_t)pl * 1024 + f, v);
        }
    }
}

// ---------------------------------------------------------------------------
extern "C" void kernel_launch(void* const* d_in, const int* in_sizes, int n_in,
                              void* d_out, int out_size)
{
    const float* points   = (const float*)d_in[0];   // [16, 512, 2]
    const float* st_sizes = (const float*)d_in[1];   // [16]
    float* out = (float*)d_out;                      // [16, 513, 4096]

    dim3 g1(CGRID / 16, NCHUNK, BFIX);               // (4, 16, 16) = 1024 blocks
    k_partial<<<g1, 256>>>(points, st_sizes, out);   // partial + fused combine
    k_write<<<BFIX * (NPTS / PGRP), 256>>>(points, out);   // 1024 blocks
}

// round 15
// speedup vs baseline: 1.3313x; 1.3313x over previous
#include <cuda_runtime.h>
#include <cuda_bf16.h>

// Fixed problem constants:
//   SIGMA=8 -> 1/(2*sigma^2)=1/128, C_SIZE=512, STRIDE=8 -> 64x64 grid,
//   cood[k]=8k+4, B=16, N=512, BG_RATIO=0.15, EPS=1e-5
//   out[b, p, i*64+j], p in [0,512], fp32, [16, 513, 4096]

#define CGRID   64
#define NPTS    512
#define PCHUNK  32
#define NCHUNK  (NPTS / PCHUNK)     // 16
#define BFIX    16
#define MPIX    (CGRID * CGRID)     // 4096
#define KINV    (1.0f / 128.0f)

// Static scratch (no runtime allocation allowed)
__device__ float g_psum[BFIX * NCHUNK * MPIX];   // 4 MB per-chunk partial sums
__device__ float g_pmax[BFIX * NCHUNK * MPIX];   // 4 MB per-chunk max products
__device__ float g_invt[BFIX * MPIX];            // 1/denominator per pixel

// ---------------------------------------------------------------------------
// K1: per (b, chunk, 16-row tile): partial exp-sum + max product (smem tables).
//     min-distance recovered later as -128*ln(max product).
//     Ey stored transposed [p][ti] -> inner-loop LDS is a clean broadcast
//     (old [ti][p] layout was 2-way bank-conflicted: the warp's two ti values
//     sat 128 B apart).
// ---------------------------------------------------------------------------
__global__ __launch_bounds__(256)
void k_partial(const float* __restrict__ points)
{
    const int b   = blockIdx.z;
    const int c   = blockIdx.y;
    const int i0  = blockIdx.x * 16;
    const int tid = threadIdx.x;
    const int ti  = tid >> 4;      // 0..15 row in tile
    const int jg  = tid & 15;      // owns j = jg*4 + {0..3}

    __shared__ float2 pts_s[PCHUNK];            // 256 B
    __shared__ float  Ex_s[PCHUNK * CGRID];     // 8 KB  [p][j]
    __shared__ float  Ey_s[PCHUNK * 16];        // 2 KB  [p][ti]  (transposed)

    const float2* ptb = (const float2*)points + b * NPTS + c * PCHUNK;
    if (tid < PCHUNK) pts_s[tid] = ptb[tid];
    __syncthreads();

    #pragma unroll
    for (int k = 0; k < (PCHUNK * CGRID) / 256; ++k) {   // 8 iters
        int idx = tid + k * 256;
        int p = idx >> 6, jj = idx & 63;
        float dx = pts_s[p].x - (float)(jj * 8 + 4);
        Ex_s[idx] = __expf(-dx * dx * KINV);
    }
    #pragma unroll
    for (int k = 0; k < (PCHUNK * 16) / 256; ++k) {      // 2 iters
        int idx = tid + k * 256;
        int p = idx >> 4, ii = idx & 15;                 // [p][ti] layout
        float dy = pts_s[p].y - (float)((i0 + ii) * 8 + 4);
        Ey_s[idx] = __expf(-dy * dy * KINV);
    }
    __syncthreads();

    float4 sum = make_float4(0.f, 0.f, 0.f, 0.f);
    float4 mx  = make_float4(0.f, 0.f, 0.f, 0.f);
    const float4* Ex4 = (const float4*)Ex_s;

    #pragma unroll 8
    for (int p = 0; p < PCHUNK; ++p) {
        float  ey = Ey_s[p * 16 + ti];          // adjacent words -> broadcast
        float4 ex = Ex4[p * 16 + jg];
        float p0 = ey * ex.x;
        float p1 = ey * ex.y;
        float p2 = ey * ex.z;
        float p3 = ey * ex.w;
        sum.x += p0; sum.y += p1; sum.z += p2; sum.w += p3;
        mx.x = fmaxf(mx.x, p0); mx.y = fmaxf(mx.y, p1);
        mx.z = fmaxf(mx.z, p2); mx.w = fmaxf(mx.w, p3);
    }

    int o = (b * NCHUNK + c) * MPIX + (i0 + ti) * CGRID + jg * 4;
    *(float4*)(g_psum + o) = sum;
    *(float4*)(g_pmax + o) = mx;
}

// ---------------------------------------------------------------------------
// K2: reduce chunk partials -> invt per pixel; write background plane p=512.
// ---------------------------------------------------------------------------
__global__ __launch_bounds__(256)
void k_combine(const float* __restrict__ st_sizes, float* __restrict__ out)
{
    int idx = blockIdx.x * 256 + threadIdx.x;       // over BFIX*MPIX/4 = 16384
    int b = idx >> 10;                               // MPIX/4 = 1024
    int r = idx & 1023;

    const float4* ps = (const float4*)g_psum;
    const float4* pm = (const float4*)g_pmax;
    int base = b * NCHUNK * 1024 + r;

    float4 sum = make_float4(0.f, 0.f, 0.f, 0.f);
    float4 mx  = make_float4(0.f, 0.f, 0.f, 0.f);
    #pragma unroll
    for (int c = 0; c < NCHUNK; ++c) {
        float4 s = ps[base + c * 1024];
        float4 m = pm[base + c * 1024];
        sum.x += s.x; sum.y += s.y; sum.z += s.z; sum.w += s.w;
        mx.x = fmaxf(mx.x, m.x); mx.y = fmaxf(mx.y, m.y);
        mx.z = fmaxf(mx.z, m.z); mx.w = fmaxf(mx.w, m.w);
    }

    float sc = st_sizes[b] * 0.15f;
    float ss = sc * sc;
    float4 invt, bgp;
    {
        float mind = -128.0f * __logf(fmaxf(mx.x, 1e-38f));
        float ebg = __expf(-(ss / (mind + 1e-5f)) * KINV);
        float iv = 1.0f / (sum.x + ebg); invt.x = iv; bgp.x = ebg * iv;
    }
    {
        float mind = -128.0f * __logf(fmaxf(mx.y, 1e-38f));
        float ebg = __expf(-(ss / (mind + 1e-5f)) * KINV);
        float iv = 1.0f / (sum.y + ebg); invt.y = iv; bgp.y = ebg * iv;
    }
    {
        float mind = -128.0f * __logf(fmaxf(mx.z, 1e-38f));
        float ebg = __expf(-(ss / (mind + 1e-5f)) * KINV);
        float iv = 1.0f / (sum.z + ebg); invt.z = iv; bgp.z = ebg * iv;
    }
    {
        float mind = -128.0f * __logf(fmaxf(mx.w, 1e-38f));
        float ebg = __expf(-(ss / (mind + 1e-5f)) * KINV);
        float iv = 1.0f / (sum.w + ebg); invt.w = iv; bgp.w = ebg * iv;
    }

    ((float4*)g_invt)[b * 1024 + r] = invt;
    __stcs(((float4*)out) + (b * 513 + 512) * 1024 + r, bgp);  // background plane
}

// ---------------------------------------------------------------------------
// K3: normalized writes. Block = (b, group of 8 planes) -> fully contiguous
//     128 KB output span per block, streaming stores. (At the effective HBM
//     write ceiling; proven best of 7 write variants.)
// ---------------------------------------------------------------------------
#define PGRP 8

__global__ __launch_bounds__(256)
void k_write(const float* __restrict__ points, float* __restrict__ out)
{
    const int b   = blockIdx.x >> 6;            // 0..15
    const int pg  = blockIdx.x & 63;            // plane group: p = pg*8 + pl
    const int tid = threadIdx.x;

    __shared__ float Ex_s[PGRP][CGRID];         // 2 KB
    __shared__ float Ey_s[PGRP][CGRID];         // 2 KB

    // Fill per-plane Ex/Ey rows: 8 planes * 64 cells * 2 tables = 1024 exps.
    #pragma unroll
    for (int k = 0; k < 4; ++k) {
        int idx  = tid + k * 256;               // 0..1023
        int pl   = idx >> 7;
        int rest = idx & 127;
        int t    = rest >> 6;                   // 0: Ex (x), 1: Ey (y)
        int cell = rest & 63;
        int p    = pg * PGRP + pl;
        float coord = points[(b * NPTS + p) * 2 + t];
        float d = coord - (float)(cell * 8 + 4);
        float e = __expf(-d * d * KINV);
        if (t) Ey_s[pl][cell] = e; else Ex_s[pl][cell] = e;
    }

    // invt for this image: each thread holds 4 float4 (covers its 4 f-slots).
    const float4* iv4 = (const float4*)g_invt + b * 1024;
    float4 invt[4];
    #pragma unroll
    for (int k = 0; k < 4; ++k)
        invt[k] = __ldg(iv4 + tid + k * 256);

    __syncthreads();

    float4* op = (float4*)out + ((size_t)b * 513 + pg * PGRP) * 1024;

    #pragma unroll
    for (int pl = 0; pl < PGRP; ++pl) {
        const float4* Ex4 = (const float4*)Ex_s[pl];
        #pragma unroll
        for (int k = 0; k < 4; ++k) {
            int f  = tid + k * 256;             // float4 index within plane
            int i  = f >> 4;
            int jg = f & 15;
            float  ey = Ey_s[pl][i];
            float4 ex = Ex4[jg];
            float4 v;
            v.x = (ey * ex.x) * invt[k].x;
            v.y = (ey * ex.y) * invt[k].y;
            v.z = (ey * ex.z) * invt[k].z;
            v.w = (ey * ex.w) * invt[k].w;
            __stcs(op + (size_t)pl * 1024 + f, v);
        }
    }
}

// ---------------------------------------------------------------------------
extern "C" void kernel_launch(void* const* d_in, const int* in_sizes, int n_in,
                              void* d_out, int out_size)
{
    const float* points   = (const float*)d_in[0];   // [16, 512, 2]
    const float* st_sizes = (const float*)d_in[1];   // [16]
    float* out = (float*)d_out;                      // [16, 513, 4096]

    dim3 g1(CGRID / 16, NCHUNK, BFIX);               // (4, 16, 16) = 1024 blocks
    k_partial<<<g1, 256>>>(points);
    k_combine<<<(BFIX * MPIX / 4) / 256, 256>>>(st_sizes, out);
    k_write<<<BFIX * (NPTS / PGRP), 256>>>(points, out);   // 1024 blocks
}

// round 16
// speedup vs baseline: 1.3808x; 1.0372x over previous
#include <cuda_runtime.h>
#include <cuda_bf16.h>

// Fixed problem constants:
//   SIGMA=8 -> 1/(2*sigma^2)=1/128, C_SIZE=512, STRIDE=8 -> 64x64 grid,
//   cood[k]=8k+4, B=16, N=512, BG_RATIO=0.15, EPS=1e-5
//   out[b, p, i*64+j], p in [0,512], fp32, [16, 513, 4096]

#define CGRID   64
#define NPTS    512
#define PCHUNK  32
#define NCHUNK  (NPTS / PCHUNK)     // 16
#define BFIX    16
#define MPIX    (CGRID * CGRID)     // 4096
#define KINV    (1.0f / 128.0f)

// Packed f32x2 helpers (sm_103a FFMA2-class; PTX-only, not emitted by ptxas
// from plain C++). .rn rounding -> bit-identical to scalar FMUL/FADD.
#define MUL_F32X2(out, a, b) \
    asm("mul.rn.f32x2 %0, %1, %2;" : "=l"(out) : "l"(a), "l"(b))
#define ADD_F32X2(out, a, b) \
    asm("add.rn.f32x2 %0, %1, %2;" : "=l"(out) : "l"(a), "l"(b))
#define PACK_F32X2(out, lo, hi) \
    asm("mov.b64 %0, {%1, %2};" : "=l"(out) : "r"(lo), "r"(hi))
#define UNPACK_F32X2(lo, hi, in) \
    asm("mov.b64 {%0, %1}, %2;" : "=r"(lo), "=r"(hi) : "l"(in))

// Static scratch (no runtime allocation allowed)
__device__ float g_psum[BFIX * NCHUNK * MPIX];   // 4 MB per-chunk partial sums
__device__ float g_pmax[BFIX * NCHUNK * MPIX];   // 4 MB per-chunk max products
__device__ float g_invt[BFIX * MPIX];            // 1/denominator per pixel

// ---------------------------------------------------------------------------
// K1: per (b, chunk, 16-row tile): partial exp-sum + max product (smem tables).
//     min-distance recovered later as -128*ln(max product).
//     Inner loop uses packed f32x2 mul/add: 2 pixels per fma-pipe instruction.
// ---------------------------------------------------------------------------
__global__ __launch_bounds__(256)
void k_partial(const float* __restrict__ points)
{
    const int b   = blockIdx.z;
    const int c   = blockIdx.y;
    const int i0  = blockIdx.x * 16;
    const int tid = threadIdx.x;
    const int ti  = tid >> 4;      // 0..15 row in tile
    const int jg  = tid & 15;      // owns j = jg*4 + {0..3}

    __shared__ float2 pts_s[PCHUNK];            // 256 B
    __shared__ float  Ex_s[PCHUNK * CGRID];     // 8 KB  [p][j]
    __shared__ float  Ey_s[16 * PCHUNK];        // 2 KB  [ti][p]

    const float2* ptb = (const float2*)points + b * NPTS + c * PCHUNK;
    if (tid < PCHUNK) pts_s[tid] = ptb[tid];
    __syncthreads();

    #pragma unroll
    for (int k = 0; k < (PCHUNK * CGRID) / 256; ++k) {   // 8 iters
        int idx = tid + k * 256;
        int p = idx >> 6, jj = idx & 63;
        float dx = pts_s[p].x - (float)(jj * 8 + 4);
        Ex_s[idx] = __expf(-dx * dx * KINV);
    }
    #pragma unroll
    for (int k = 0; k < (16 * PCHUNK) / 256; ++k) {      // 2 iters
        int idx = tid + k * 256;
        int ii = idx >> 5, p = idx & (PCHUNK - 1);
        float dy = pts_s[p].y - (float)((i0 + ii) * 8 + 4);
        Ey_s[idx] = __expf(-dy * dy * KINV);
    }
    __syncthreads();

    unsigned long long s01 = 0ull, s23 = 0ull;   // packed (sum0,sum1),(sum2,sum3)
    float4 mx = make_float4(0.f, 0.f, 0.f, 0.f);
    const ulonglong2* Exp = (const ulonglong2*)Ex_s;   // LDS.128 as 2x f32x2

    #pragma unroll 8
    for (int p = 0; p < PCHUNK; ++p) {
        float ey = Ey_s[ti * PCHUNK + p];
        unsigned long long ey2;
        PACK_F32X2(ey2, __float_as_uint(ey), __float_as_uint(ey));

        ulonglong2 ex2 = Exp[p * 16 + jg];

        unsigned long long p01, p23;
        MUL_F32X2(p01, ex2.x, ey2);
        MUL_F32X2(p23, ex2.y, ey2);
        ADD_F32X2(s01, s01, p01);
        ADD_F32X2(s23, s23, p23);

        unsigned int u0, u1, u2, u3;
        UNPACK_F32X2(u0, u1, p01);
        UNPACK_F32X2(u2, u3, p23);
        mx.x = fmaxf(mx.x, __uint_as_float(u0));
        mx.y = fmaxf(mx.y, __uint_as_float(u1));
        mx.z = fmaxf(mx.z, __uint_as_float(u2));
        mx.w = fmaxf(mx.w, __uint_as_float(u3));
    }

    float4 sum;
    {
        unsigned int a, bq, cq, d;
        UNPACK_F32X2(a, bq, s01);
        UNPACK_F32X2(cq, d, s23);
        sum.x = __uint_as_float(a);
        sum.y = __uint_as_float(bq);
        sum.z = __uint_as_float(cq);
        sum.w = __uint_as_float(d);
    }

    int o = (b * NCHUNK + c) * MPIX + (i0 + ti) * CGRID + jg * 4;
    *(float4*)(g_psum + o) = sum;
    *(float4*)(g_pmax + o) = mx;
}

// ---------------------------------------------------------------------------
// K2: reduce chunk partials -> invt per pixel; write background plane p=512.
// ---------------------------------------------------------------------------
__global__ __launch_bounds__(256)
void k_combine(const float* __restrict__ st_sizes, float* __restrict__ out)
{
    int idx = blockIdx.x * 256 + threadIdx.x;       // over BFIX*MPIX/4 = 16384
    int b = idx >> 10;                               // MPIX/4 = 1024
    int r = idx & 1023;

    const float4* ps = (const float4*)g_psum;
    const float4* pm = (const float4*)g_pmax;
    int base = b * NCHUNK * 1024 + r;

    float4 sum = make_float4(0.f, 0.f, 0.f, 0.f);
    float4 mx  = make_float4(0.f, 0.f, 0.f, 0.f);
    #pragma unroll
    for (int c = 0; c < NCHUNK; ++c) {
        float4 s = ps[base + c * 1024];
        float4 m = pm[base + c * 1024];
        sum.x += s.x; sum.y += s.y; sum.z += s.z; sum.w += s.w;
        mx.x = fmaxf(mx.x, m.x); mx.y = fmaxf(mx.y, m.y);
        mx.z = fmaxf(mx.z, m.z); mx.w = fmaxf(mx.w, m.w);
    }

    float sc = st_sizes[b] * 0.15f;
    float ss = sc * sc;
    float4 invt, bgp;
    {
        float mind = -128.0f * __logf(fmaxf(mx.x, 1e-38f));
        float ebg = __expf(-(ss / (mind + 1e-5f)) * KINV);
        float iv = 1.0f / (sum.x + ebg); invt.x = iv; bgp.x = ebg * iv;
    }
    {
        float mind = -128.0f * __logf(fmaxf(mx.y, 1e-38f));
        float ebg = __expf(-(ss / (mind + 1e-5f)) * KINV);
        float iv = 1.0f / (sum.y + ebg); invt.y = iv; bgp.y = ebg * iv;
    }
    {
        float mind = -128.0f * __logf(fmaxf(mx.z, 1e-38f));
        float ebg = __expf(-(ss / (mind + 1e-5f)) * KINV);
        float iv = 1.0f / (sum.z + ebg); invt.z = iv; bgp.z = ebg * iv;
    }
    {
        float mind = -128.0f * __logf(fmaxf(mx.w, 1e-38f));
        float ebg = __expf(-(ss / (mind + 1e-5f)) * KINV);
        float iv = 1.0f / (sum.w + ebg); invt.w = iv; bgp.w = ebg * iv;
    }

    ((float4*)g_invt)[b * 1024 + r] = invt;
    __stcs(((float4*)out) + (b * 513 + 512) * 1024 + r, bgp);  // background plane
}

// ---------------------------------------------------------------------------
// K3: normalized writes. Block = (b, group of 8 planes) -> fully contiguous
//     128 KB output span per block, streaming stores. (At the effective HBM
//     write ceiling; proven best of 7 write variants.)
// ---------------------------------------------------------------------------
#define PGRP 8

__global__ __launch_bounds__(256)
void k_write(const float* __restrict__ points, float* __restrict__ out)
{
    const int b   = blockIdx.x >> 6;            // 0..15
    const int pg  = blockIdx.x & 63;            // plane group: p = pg*8 + pl
    const int tid = threadIdx.x;

    __shared__ float Ex_s[PGRP][CGRID];         // 2 KB
    __shared__ float Ey_s[PGRP][CGRID];         // 2 KB

    // Fill per-plane Ex/Ey rows: 8 planes * 64 cells * 2 tables = 1024 exps.
    #pragma unroll
    for (int k = 0; k < 4; ++k) {
        int idx  = tid + k * 256;               // 0..1023
        int pl   = idx >> 7;
        int rest = idx & 127;
        int t    = rest >> 6;                   // 0: Ex (x), 1: Ey (y)
        int cell = rest & 63;
        int p    = pg * PGRP + pl;
        float coord = points[(b * NPTS + p) * 2 + t];
        float d = coord - (float)(cell * 8 + 4);
        float e = __expf(-d * d * KINV);
        if (t) Ey_s[pl][cell] = e; else Ex_s[pl][cell] = e;
    }

    // invt for this image: each thread holds 4 float4 (covers its 4 f-slots).
    const float4* iv4 = (const float4*)g_invt + b * 1024;
    float4 invt[4];
    #pragma unroll
    for (int k = 0; k < 4; ++k)
        invt[k] = __ldg(iv4 + tid + k * 256);

    __syncthreads();

    float4* op = (float4*)out + ((size_t)b * 513 + pg * PGRP) * 1024;

    #pragma unroll
    for (int pl = 0; pl < PGRP; ++pl) {
        const float4* Ex4 = (const float4*)Ex_s[pl];
        #pragma unroll
        for (int k = 0; k < 4; ++k) {
            int f  = tid + k * 256;             // float4 index within plane
            int i  = f >> 4;
            int jg = f & 15;
            float  ey = Ey_s[pl][i];
            float4 ex = Ex4[jg];
            float4 v;
            v.x = (ey * ex.x) * invt[k].x;
            v.y = (ey * ex.y) * invt[k].y;
            v.z = (ey * ex.z) * invt[k].z;
            v.w = (ey * ex.w) * invt[k].w;
            __stcs(op + (size_t)pl * 1024 + f, v);
        }
    }
}

// ---------------------------------------------------------------------------
extern "C" void kernel_launch(void* const* d_in, const int* in_sizes, int n_in,
                              void* d_out, int out_size)
{
    const float* points   = (const float*)d_in[0];   // [16, 512, 2]
    const float* st_sizes = (const float*)d_in[1];   // [16]
    float* out = (float*)d_out;                      // [16, 513, 4096]

    dim3 g1(CGRID / 16, NCHUNK, BFIX);               // (4, 16, 16) = 1024 blocks
    k_partial<<<g1, 256>>>(points);
    k_combine<<<(BFIX * MPIX / 4) / 256, 256>>>(st_sizes, out);
    k_write<<<BFIX * (NPTS / PGRP), 256>>>(points, out);   // 1024 blocks
}